// round 12
// baseline (speedup 1.0000x reference)
#include <cuda_runtime.h>
#include <cuda_fp16.h>
#include <math.h>

#define C_CH 256
#define NBIN 49

// Channels-last fp16 scratch for the 4 FPN levels (B=2 fixed by problem).
__device__ __half g_h0[2 * 200 * 200 * C_CH];
__device__ __half g_h1[2 * 100 * 100 * C_CH];
__device__ __half g_h2[2 * 50  * 50  * C_CH];
__device__ __half g_h3[2 * 25  * 25  * C_CH];

// Fused transpose: [B,C,HW] fp32 -> [B,HW,C] fp16, all 4 levels in ONE launch.
// Tile = 64ch x 32px per block (256 threads).
// Phase A: LDG.128 (4 px) -> 4x STS.32 into fp32 tile [32px][68].
// Phase B: LDS.128 (4 ch)  -> 2x F2FP.PACK -> STG.64.
// LDG.128 path requires HW % 4 == 0; level 3 (HW=625) takes scalar fallback.
__global__ __launch_bounds__(256) void transpose_all(const float* __restrict__ f0,
                                                     const float* __restrict__ f1,
                                                     const float* __restrict__ f2,
                                                     const float* __restrict__ f3,
                                                     int B) {
    __shared__ __align__(16) float tile[32][68];

    const int HWs[4] = {200 * 200, 100 * 100, 50 * 50, 25 * 25};
    int idx = blockIdx.x;
    int l = 0, nPx = 0;
    #pragma unroll
    for (int q = 0; q < 4; ++q) {
        nPx = (HWs[q] + 31) / 32;
        int nb = nPx * (C_CH / 64) * B;
        if (idx < nb) { l = q; break; }
        idx -= nb;
    }
    int HW = HWs[l];
    const float* in = (l == 0) ? f0 : (l == 1) ? f1 : (l == 2) ? f2 : f3;
    __half* outp    = (l == 0) ? g_h0 : (l == 1) ? g_h1 : (l == 2) ? g_h2 : g_h3;

    int pt = idx % nPx;
    int r  = idx / nPx;
    int cg = r % (C_CH / 64);
    int b  = r / (C_CH / 64);

    int p0 = pt * 32;
    int c0 = cg * 64;
    const float* ib = in   + (size_t)b * C_CH * HW;
    __half*      ob = outp + (size_t)b * C_CH * HW;
    int t = threadIdx.x;

    {
        int g  = t & 7;
        int ch = t >> 3;
        int p  = p0 + 4 * g;
        bool full = (p0 + 32 <= HW) && ((HW & 3) == 0);
        #pragma unroll
        for (int pass = 0; pass < 2; ++pass) {
            int c = ch + pass * 32;
            const float* src = ib + (size_t)(c0 + c) * HW + p;
            if (full) {
                float4 v = __ldcs((const float4*)src);
                tile[4 * g + 0][c] = v.x;
                tile[4 * g + 1][c] = v.y;
                tile[4 * g + 2][c] = v.z;
                tile[4 * g + 3][c] = v.w;
            } else {
                #pragma unroll
                for (int k = 0; k < 4; ++k)
                    tile[4 * g + k][c] = (p + k < HW) ? __ldcs(src + k) : 0.0f;
            }
        }
    }
    __syncthreads();

    {
        int lane = t & 31;
        int w    = t >> 5;
        int cq   = lane & 15;
        int ph   = lane >> 4;
        #pragma unroll
        for (int j = 0; j < 2; ++j) {
            int px = w * 4 + j * 2 + ph;
            int pg = p0 + px;
            if (pg < HW) {
                float4 v = *reinterpret_cast<const float4*>(&tile[px][4 * cq]);
                __half2 h0 = __floats2half2_rn(v.x, v.y);
                __half2 h1 = __floats2half2_rn(v.z, v.w);
                uint2 pk;
                pk.x = *reinterpret_cast<unsigned*>(&h0);
                pk.y = *reinterpret_cast<unsigned*>(&h1);
                *reinterpret_cast<uint2*>(ob + (size_t)pg * C_CH + c0 + 4 * cq) = pk;
            }
        }
    }
}

// One 448-thread block per (box, output-row): 14 warps, warp = (bin, half).
// Each warp handles only 2 tap-groups (8 taps) of its bin -> ~2 serialized
// L2-latency rounds on the critical path (halved vs warp-per-bin). Lane owns
// 8 channels via uint4 (LDG.128). Partials staged in fp32 smem per half;
// cross-half sum at the coalesced writeout.
__global__ __launch_bounds__(448, 3) void roi_main(const float* __restrict__ props,
                                                   float* __restrict__ out,
                                                   int Np) {
    __shared__ __align__(16) float stage[2][7][260];  // [half][bx][c]
    __shared__ uint4 s_off[28];   // [bxi*4+g] -> 4 tap pixel-offsets (uint4 units)
    __shared__ uint4 s_w[28];     // [bxi*4+g] -> 4 duplicated-half2 weights (x0.25)
    __shared__ int   s_xlo[14], s_xhi[14];
    __shared__ float s_xfr[14], s_xva[14];
    __shared__ int   s_ylo[2],  s_yhi[2];
    __shared__ float s_yfr[2],  s_yva[2];

    int n  = blockIdx.x;
    int by = blockIdx.y;
    int t  = threadIdx.x;

    float bx0 = props[n * 4 + 0];
    float by0 = props[n * 4 + 1];
    float bx1 = props[n * 4 + 2];
    float by1 = props[n * 4 + 3];

    float s  = sqrtf((bx1 - bx0) * (by1 - by0));
    float lv = floorf(4.0f + log2f(s * (1.0f / 224.0f) + 1e-6f));
    lv = fminf(fmaxf(lv, 2.0f), 5.0f);
    int l = (int)lv - 2;

    int H;
    float scale;
    const __half* fp;
    if      (l == 0) { H = 200; scale = 0.25f;    fp = g_h0; }
    else if (l == 1) { H = 100; scale = 0.125f;   fp = g_h1; }
    else if (l == 2) { H = 50;  scale = 0.0625f;  fp = g_h2; }
    else             { H = 25;  scale = 0.03125f; fp = g_h3; }
    int W = H;
    int bidx = n / Np;

    // Sample prep: threads 0..13 -> x samples, 14..15 -> the 2 y samples of this row.
    if (t < 16) {
        bool isY = (t >= 14);
        int  k   = isY ? (2 * by + (t - 14)) : t;
        float off = (float)(k >> 1) + ((float)(k & 1) + 0.5f) * 0.5f;
        float c0  = (isY ? by0 : bx0) * scale;
        float c1  = (isY ? by1 : bx1) * scale;
        float bin = fmaxf(c1 - c0, 1.0f) * (1.0f / 7.0f);
        float c   = c0 + off * bin;
        float valid = (c >= -1.0f && c <= (float)H) ? 1.0f : 0.0f;
        float cc  = fmaxf(c, 0.0f);
        int   lo0 = (int)floorf(cc);
        bool  edge = (lo0 >= H - 1);
        int lo = edge ? (H - 1) : lo0;
        int hi = edge ? (H - 1) : (lo0 + 1);
        float fr = edge ? 0.0f : (cc - (float)lo0);
        if (isY) { int q = t - 14; s_ylo[q] = lo; s_yhi[q] = hi; s_yfr[q] = fr; s_yva[q] = valid; }
        else     {                 s_xlo[t] = lo; s_xhi[t] = hi; s_xfr[t] = fr; s_xva[t] = valid; }
    }
    __syncthreads();

    // Precompute 112 taps: i = bxi*16 + g*4 + tap; g = (sy,sx) group.
    if (t < 112) {
        int i = t;
        int bxi = i >> 4, r = i & 15, g = r >> 2, tap = r & 3;
        int sy = g >> 1, sx = g & 1;
        int kx = 2 * bxi + sx;
        int row = (tap & 2) ? s_yhi[sy] : s_ylo[sy];
        int x   = (tap & 1) ? s_xhi[kx] : s_xlo[kx];
        float wy = (tap & 2) ? s_yfr[sy] : (1.0f - s_yfr[sy]);
        float wx = (tap & 1) ? s_xfr[kx] : (1.0f - s_xfr[kx]);
        float w  = s_yva[sy] * s_xva[kx] * wy * wx * 0.25f;   // fold sample mean
        ((unsigned*)s_off)[i] = (unsigned)((row * W + x) * (C_CH / 8));
        unsigned hb = (unsigned)__half_as_ushort(__float2half_rn(w));
        ((unsigned*)s_w)[i] = hb | (hb << 16);
    }
    __syncthreads();

    int w    = t >> 5;        // warp 0..13
    int bxi  = w >> 1;        // bin 0..6
    int half = w & 1;         // tap-group half
    int lane = t & 31;

    const uint4* fb = (const uint4*)(fp + (size_t)bidx * H * W * C_CH) + lane;

    __half2 a0 = __float2half2_rn(0.0f);
    __half2 a1 = a0, a2 = a0, a3 = a0;

    #pragma unroll
    for (int gg = 0; gg < 2; ++gg) {
        int g = half * 2 + gg;
        uint4 off = s_off[bxi * 4 + g];
        uint4 wq  = s_w[bxi * 4 + g];
        uint4 v0 = __ldg(fb + off.x);
        uint4 v1 = __ldg(fb + off.y);
        uint4 v2 = __ldg(fb + off.z);
        uint4 v3 = __ldg(fb + off.w);
        __half2 w0 = *reinterpret_cast<const __half2*>(&wq.x);
        __half2 w1 = *reinterpret_cast<const __half2*>(&wq.y);
        __half2 w2 = *reinterpret_cast<const __half2*>(&wq.z);
        __half2 w3 = *reinterpret_cast<const __half2*>(&wq.w);
        a0 = __hfma2(*reinterpret_cast<const __half2*>(&v0.x), w0, a0);
        a1 = __hfma2(*reinterpret_cast<const __half2*>(&v0.y), w0, a1);
        a2 = __hfma2(*reinterpret_cast<const __half2*>(&v0.z), w0, a2);
        a3 = __hfma2(*reinterpret_cast<const __half2*>(&v0.w), w0, a3);
        a0 = __hfma2(*reinterpret_cast<const __half2*>(&v1.x), w1, a0);
        a1 = __hfma2(*reinterpret_cast<const __half2*>(&v1.y), w1, a1);
        a2 = __hfma2(*reinterpret_cast<const __half2*>(&v1.z), w1, a2);
        a3 = __hfma2(*reinterpret_cast<const __half2*>(&v1.w), w1, a3);
        a0 = __hfma2(*reinterpret_cast<const __half2*>(&v2.x), w2, a0);
        a1 = __hfma2(*reinterpret_cast<const __half2*>(&v2.y), w2, a1);
        a2 = __hfma2(*reinterpret_cast<const __half2*>(&v2.z), w2, a2);
        a3 = __hfma2(*reinterpret_cast<const __half2*>(&v2.w), w2, a3);
        a0 = __hfma2(*reinterpret_cast<const __half2*>(&v3.x), w3, a0);
        a1 = __hfma2(*reinterpret_cast<const __half2*>(&v3.y), w3, a1);
        a2 = __hfma2(*reinterpret_cast<const __half2*>(&v3.z), w3, a2);
        a3 = __hfma2(*reinterpret_cast<const __half2*>(&v3.w), w3, a3);
    }
    float2 f0v = __half22float2(a0);
    float2 f1v = __half22float2(a1);
    float2 f2v = __half22float2(a2);
    float2 f3v = __half22float2(a3);
    *reinterpret_cast<float4*>(&stage[half][bxi][8 * lane]) =
        make_float4(f0v.x, f0v.y, f1v.x, f1v.y);
    *reinterpret_cast<float4*>(&stage[half][bxi][8 * lane + 4]) =
        make_float4(f2v.x, f2v.y, f3v.x, f3v.y);
    __syncthreads();

    // Write this row: out[n, c, by, bx] for all c, bx. j = c*7 + bx keeps
    // global writes contiguous across lanes. Cross-half fp32 sum here.
    float* orow = out + (size_t)n * (C_CH * NBIN) + by * 7;
    #pragma unroll
    for (int j = t; j < C_CH * 7; j += 448) {
        int c  = j / 7;
        int bx = j - c * 7;
        orow[c * NBIN + bx] = stage[0][bx][c] + stage[1][bx][c];
    }
}

extern "C" void kernel_launch(void* const* d_in, const int* in_sizes, int n_in,
                              void* d_out, int out_size) {
    const float* f0    = (const float*)d_in[0];
    const float* f1    = (const float*)d_in[1];
    const float* f2    = (const float*)d_in[2];
    const float* f3    = (const float*)d_in[3];
    const float* props = (const float*)d_in[4];

    int B  = in_sizes[0] / (C_CH * 200 * 200);
    int Np = in_sizes[4] / (4 * B);
    int Nb = B * Np;

    int total = 0;
    const int HWs[4] = {200 * 200, 100 * 100, 50 * 50, 25 * 25};
    for (int l = 0; l < 4; ++l)
        total += ((HWs[l] + 31) / 32) * (C_CH / 64) * B;

    transpose_all<<<total, 256>>>(f0, f1, f2, f3, B);

    dim3 grd(Nb, 7);
    roi_main<<<grd, 448>>>(props, (float*)d_out, Np);
}

// round 13
// speedup vs baseline: 1.1309x; 1.1309x over previous
#include <cuda_runtime.h>
#include <cuda_fp16.h>
#include <math.h>

#define C_CH 256
#define NBIN 49

// Channels-last fp16 scratch for the 4 FPN levels (B=2 fixed by problem).
__device__ __half g_h0[2 * 200 * 200 * C_CH];
__device__ __half g_h1[2 * 100 * 100 * C_CH];
__device__ __half g_h2[2 * 50  * 50  * C_CH];
__device__ __half g_h3[2 * 25  * 25  * C_CH];

// Fused transpose: [B,C,HW] fp32 -> [B,HW,C] fp16, all 4 levels in ONE launch.
// Tile = 64ch x 32px per block (256 threads).
// Phase A: LDG.128 (4 px) -> 4x STS.32 into fp32 tile [32px][68].
// Phase B: LDS.128 (4 ch)  -> 2x F2FP.PACK -> STG.64.
// LDG.128 path requires HW % 4 == 0; level 3 (HW=625) takes scalar fallback.
__global__ __launch_bounds__(256) void transpose_all(const float* __restrict__ f0,
                                                     const float* __restrict__ f1,
                                                     const float* __restrict__ f2,
                                                     const float* __restrict__ f3,
                                                     int B) {
    __shared__ __align__(16) float tile[32][68];

    const int HWs[4] = {200 * 200, 100 * 100, 50 * 50, 25 * 25};
    int idx = blockIdx.x;
    int l = 0, nPx = 0;
    #pragma unroll
    for (int q = 0; q < 4; ++q) {
        nPx = (HWs[q] + 31) / 32;
        int nb = nPx * (C_CH / 64) * B;
        if (idx < nb) { l = q; break; }
        idx -= nb;
    }
    int HW = HWs[l];
    const float* in = (l == 0) ? f0 : (l == 1) ? f1 : (l == 2) ? f2 : f3;
    __half* outp    = (l == 0) ? g_h0 : (l == 1) ? g_h1 : (l == 2) ? g_h2 : g_h3;

    int pt = idx % nPx;
    int r  = idx / nPx;
    int cg = r % (C_CH / 64);
    int b  = r / (C_CH / 64);

    int p0 = pt * 32;
    int c0 = cg * 64;
    const float* ib = in   + (size_t)b * C_CH * HW;
    __half*      ob = outp + (size_t)b * C_CH * HW;
    int t = threadIdx.x;

    {
        int g  = t & 7;
        int ch = t >> 3;
        int p  = p0 + 4 * g;
        bool full = (p0 + 32 <= HW) && ((HW & 3) == 0);
        #pragma unroll
        for (int pass = 0; pass < 2; ++pass) {
            int c = ch + pass * 32;
            const float* src = ib + (size_t)(c0 + c) * HW + p;
            if (full) {
                float4 v = __ldcs((const float4*)src);
                tile[4 * g + 0][c] = v.x;
                tile[4 * g + 1][c] = v.y;
                tile[4 * g + 2][c] = v.z;
                tile[4 * g + 3][c] = v.w;
            } else {
                #pragma unroll
                for (int k = 0; k < 4; ++k)
                    tile[4 * g + k][c] = (p + k < HW) ? __ldcs(src + k) : 0.0f;
            }
        }
    }
    __syncthreads();

    {
        int lane = t & 31;
        int w    = t >> 5;
        int cq   = lane & 15;
        int ph   = lane >> 4;
        #pragma unroll
        for (int j = 0; j < 2; ++j) {
            int px = w * 4 + j * 2 + ph;
            int pg = p0 + px;
            if (pg < HW) {
                float4 v = *reinterpret_cast<const float4*>(&tile[px][4 * cq]);
                __half2 h0 = __floats2half2_rn(v.x, v.y);
                __half2 h1 = __floats2half2_rn(v.z, v.w);
                uint2 pk;
                pk.x = *reinterpret_cast<unsigned*>(&h0);
                pk.y = *reinterpret_cast<unsigned*>(&h1);
                *reinterpret_cast<uint2*>(ob + (size_t)pg * C_CH + c0 + 4 * cq) = pk;
            }
        }
    }
}

// One 224-thread block per (box, output-row): warp w = bin w (NO serial bin
// loop). Lane owns 8 channels {8*lane..8*lane+7} via uint4 (LDG.128) per tap.
// Tap table (offsets + duplicated-half2 weights, x0.25 prefolded) built once
// per block in smem. 16-tap bin accumulated in half2, fp32 convert once.
// launch_bounds(224,7): 7 blocks x 224thr x 40regs = 62720 <= 64K -> 49 warps/SM.
__global__ __launch_bounds__(224, 7) void roi_main(const float* __restrict__ props,
                                                   float* __restrict__ out,
                                                   int Np) {
    __shared__ __align__(16) float stage[7 * 260];   // [bx][c], stride 260
    __shared__ uint4 s_off[28];   // [bxi*4+g] -> 4 tap pixel-offsets (uint4 units)
    __shared__ uint4 s_w[28];     // [bxi*4+g] -> 4 duplicated-half2 weights (x0.25)
    __shared__ int   s_xlo[14], s_xhi[14];
    __shared__ float s_xfr[14], s_xva[14];
    __shared__ int   s_ylo[2],  s_yhi[2];
    __shared__ float s_yfr[2],  s_yva[2];

    int n  = blockIdx.x;
    int by = blockIdx.y;
    int t  = threadIdx.x;

    float bx0 = props[n * 4 + 0];
    float by0 = props[n * 4 + 1];
    float bx1 = props[n * 4 + 2];
    float by1 = props[n * 4 + 3];

    float s  = sqrtf((bx1 - bx0) * (by1 - by0));
    float lv = floorf(4.0f + log2f(s * (1.0f / 224.0f) + 1e-6f));
    lv = fminf(fmaxf(lv, 2.0f), 5.0f);
    int l = (int)lv - 2;

    int H;
    float scale;
    const __half* fp;
    if      (l == 0) { H = 200; scale = 0.25f;    fp = g_h0; }
    else if (l == 1) { H = 100; scale = 0.125f;   fp = g_h1; }
    else if (l == 2) { H = 50;  scale = 0.0625f;  fp = g_h2; }
    else             { H = 25;  scale = 0.03125f; fp = g_h3; }
    int W = H;
    int bidx = n / Np;

    // Sample prep: threads 0..13 -> x samples, 14..15 -> the 2 y samples of this row.
    if (t < 16) {
        bool isY = (t >= 14);
        int  k   = isY ? (2 * by + (t - 14)) : t;
        float off = (float)(k >> 1) + ((float)(k & 1) + 0.5f) * 0.5f;
        float c0  = (isY ? by0 : bx0) * scale;
        float c1  = (isY ? by1 : bx1) * scale;
        float bin = fmaxf(c1 - c0, 1.0f) * (1.0f / 7.0f);
        float c   = c0 + off * bin;
        float valid = (c >= -1.0f && c <= (float)H) ? 1.0f : 0.0f;
        float cc  = fmaxf(c, 0.0f);
        int   lo0 = (int)floorf(cc);
        bool  edge = (lo0 >= H - 1);
        int lo = edge ? (H - 1) : lo0;
        int hi = edge ? (H - 1) : (lo0 + 1);
        float fr = edge ? 0.0f : (cc - (float)lo0);
        if (isY) { int q = t - 14; s_ylo[q] = lo; s_yhi[q] = hi; s_yfr[q] = fr; s_yva[q] = valid; }
        else     {                 s_xlo[t] = lo; s_xhi[t] = hi; s_xfr[t] = fr; s_xva[t] = valid; }
    }
    __syncthreads();

    // Precompute 112 taps: i = bxi*16 + g*4 + tap; g = (sy,sx) group.
    if (t < 112) {
        int i = t;
        int bxi = i >> 4, r = i & 15, g = r >> 2, tap = r & 3;
        int sy = g >> 1, sx = g & 1;
        int kx = 2 * bxi + sx;
        int row = (tap & 2) ? s_yhi[sy] : s_ylo[sy];
        int x   = (tap & 1) ? s_xhi[kx] : s_xlo[kx];
        float wy = (tap & 2) ? s_yfr[sy] : (1.0f - s_yfr[sy]);
        float wx = (tap & 1) ? s_xfr[kx] : (1.0f - s_xfr[kx]);
        float w  = s_yva[sy] * s_xva[kx] * wy * wx * 0.25f;   // fold sample mean
        ((unsigned*)s_off)[i] = (unsigned)((row * W + x) * (C_CH / 8));
        unsigned hb = (unsigned)__half_as_ushort(__float2half_rn(w));
        ((unsigned*)s_w)[i] = hb | (hb << 16);
    }
    __syncthreads();

    int bxi  = t >> 5;        // warp = bin (0..6)
    int lane = t & 31;

    const uint4* fb = (const uint4*)(fp + (size_t)bidx * H * W * C_CH) + lane;

    __half2 a0 = __float2half2_rn(0.0f);
    __half2 a1 = a0, a2 = a0, a3 = a0;

    #pragma unroll
    for (int g = 0; g < 4; ++g) {
        uint4 off = s_off[bxi * 4 + g];
        uint4 wq  = s_w[bxi * 4 + g];
        uint4 v0 = __ldg(fb + off.x);
        uint4 v1 = __ldg(fb + off.y);
        uint4 v2 = __ldg(fb + off.z);
        uint4 v3 = __ldg(fb + off.w);
        __half2 w0 = *reinterpret_cast<const __half2*>(&wq.x);
        __half2 w1 = *reinterpret_cast<const __half2*>(&wq.y);
        __half2 w2 = *reinterpret_cast<const __half2*>(&wq.z);
        __half2 w3 = *reinterpret_cast<const __half2*>(&wq.w);
        a0 = __hfma2(*reinterpret_cast<const __half2*>(&v0.x), w0, a0);
        a1 = __hfma2(*reinterpret_cast<const __half2*>(&v0.y), w0, a1);
        a2 = __hfma2(*reinterpret_cast<const __half2*>(&v0.z), w0, a2);
        a3 = __hfma2(*reinterpret_cast<const __half2*>(&v0.w), w0, a3);
        a0 = __hfma2(*reinterpret_cast<const __half2*>(&v1.x), w1, a0);
        a1 = __hfma2(*reinterpret_cast<const __half2*>(&v1.y), w1, a1);
        a2 = __hfma2(*reinterpret_cast<const __half2*>(&v1.z), w1, a2);
        a3 = __hfma2(*reinterpret_cast<const __half2*>(&v1.w), w1, a3);
        a0 = __hfma2(*reinterpret_cast<const __half2*>(&v2.x), w2, a0);
        a1 = __hfma2(*reinterpret_cast<const __half2*>(&v2.y), w2, a1);
        a2 = __hfma2(*reinterpret_cast<const __half2*>(&v2.z), w2, a2);
        a3 = __hfma2(*reinterpret_cast<const __half2*>(&v2.w), w2, a3);
        a0 = __hfma2(*reinterpret_cast<const __half2*>(&v3.x), w3, a0);
        a1 = __hfma2(*reinterpret_cast<const __half2*>(&v3.y), w3, a1);
        a2 = __hfma2(*reinterpret_cast<const __half2*>(&v3.z), w3, a2);
        a3 = __hfma2(*reinterpret_cast<const __half2*>(&v3.w), w3, a3);
    }
    float2 f0v = __half22float2(a0);
    float2 f1v = __half22float2(a1);
    float2 f2v = __half22float2(a2);
    float2 f3v = __half22float2(a3);
    *reinterpret_cast<float4*>(&stage[bxi * 260 + 8 * lane]) =
        make_float4(f0v.x, f0v.y, f1v.x, f1v.y);
    *reinterpret_cast<float4*>(&stage[bxi * 260 + 8 * lane + 4]) =
        make_float4(f2v.x, f2v.y, f3v.x, f3v.y);
    __syncthreads();

    // Write this row: out[n, c, by, bx] for all c, bx. j = c*7 + bx contiguous
    // across lanes; incremental c/bx avoids integer division in the loop.
    float* orow = out + (size_t)n * (C_CH * NBIN) + by * 7;
    {
        int c  = t / 7;
        int bx = t - c * 7;
        #pragma unroll
        for (int it = 0; it < 8; ++it) {
            orow[c * NBIN + bx] = stage[bx * 260 + c];
            c += 32;            // 224 threads / 7 bins = 32 channels per step
        }
    }
}

extern "C" void kernel_launch(void* const* d_in, const int* in_sizes, int n_in,
                              void* d_out, int out_size) {
    const float* f0    = (const float*)d_in[0];
    const float* f1    = (const float*)d_in[1];
    const float* f2    = (const float*)d_in[2];
    const float* f3    = (const float*)d_in[3];
    const float* props = (const float*)d_in[4];

    int B  = in_sizes[0] / (C_CH * 200 * 200);
    int Np = in_sizes[4] / (4 * B);
    int Nb = B * Np;

    int total = 0;
    const int HWs[4] = {200 * 200, 100 * 100, 50 * 50, 25 * 25};
    for (int l = 0; l < 4; ++l)
        total += ((HWs[l] + 31) / 32) * (C_CH / 64) * B;

    transpose_all<<<total, 256>>>(f0, f1, f2, f3, B);

    dim3 grd(Nb, 7);
    roi_main<<<grd, 224>>>(props, (float*)d_out, Np);
}